// round 6
// baseline (speedup 1.0000x reference)
#include <cuda_runtime.h>

// out[row, :] = W[ids[row], :]
// W: [50257, 1024] fp32, ids: [32768] int32, out: [32768, 1024] fp32
// 8 rows per CTA, 256 threads. Each thread moves 4 independent 32-byte
// chunks (ld.v4.b64 / st.v4.b64 — required width for L2 eviction hints on
// sm_103). Weight loads are L2::evict_last (sticky: ~98MB of distinct
// gathered rows fit in 126MB L2 and repeat across graph replays); output
// stores are L2::evict_first so the write-once stream doesn't evict them.

struct V32 { unsigned long long a, b, c, d; };

__device__ __forceinline__ V32 ldg_evict_last(const V32* p) {
    V32 v;
    asm volatile("ld.global.nc.L2::evict_last.v4.b64 {%0,%1,%2,%3}, [%4];"
                 : "=l"(v.a), "=l"(v.b), "=l"(v.c), "=l"(v.d)
                 : "l"(p));
    return v;
}

__device__ __forceinline__ void stg_evict_first(V32* p, V32 v) {
    asm volatile("st.global.L2::evict_first.v4.b64 [%0], {%1,%2,%3,%4};"
                 :: "l"(p), "l"(v.a), "l"(v.b), "l"(v.c), "l"(v.d)
                 : "memory");
}

__global__ void __launch_bounds__(256)
embed_gather_kernel(const V32* __restrict__ w,
                    const int* __restrict__ ids,
                    V32* __restrict__ out)
{
    // Row = 1024 floats = 4096 B = 128 chunks of 32 B.
    const int row0 = blockIdx.x * 8;
    const int sub  = threadIdx.x >> 7;        // 0..1: which row within a pair
    const int c    = threadIdx.x & 127;       // chunk within row

    const int r0 = row0 + 0 + sub;
    const int r1 = row0 + 2 + sub;
    const int r2 = row0 + 4 + sub;
    const int r3 = row0 + 6 + sub;

    const long long id0 = (long long)ids[r0];
    const long long id1 = (long long)ids[r1];
    const long long id2 = (long long)ids[r2];
    const long long id3 = (long long)ids[r3];

    // 4 independent 32B gathers — all issued before any consumer.
    const V32 v0 = ldg_evict_last(w + id0 * 128 + c);
    const V32 v1 = ldg_evict_last(w + id1 * 128 + c);
    const V32 v2 = ldg_evict_last(w + id2 * 128 + c);
    const V32 v3 = ldg_evict_last(w + id3 * 128 + c);

    stg_evict_first(out + (long long)r0 * 128 + c, v0);
    stg_evict_first(out + (long long)r1 * 128 + c, v1);
    stg_evict_first(out + (long long)r2 * 128 + c, v2);
    stg_evict_first(out + (long long)r3 * 128 + c, v3);
}

extern "C" void kernel_launch(void* const* d_in, const int* in_sizes, int n_in,
                              void* d_out, int out_size)
{
    // Resolve input order by element count: weight = 50257*1024, ids = 32768.
    int wi = 0, ii = 1;
    if (in_sizes[0] < in_sizes[1]) { wi = 1; ii = 0; }

    const V32* w    = (const V32*)d_in[wi];
    const int* ids  = (const int*)d_in[ii];
    const int n_rows = in_sizes[ii];          // 32768, divisible by 8

    V32* out = (V32*)d_out;
    embed_gather_kernel<<<n_rows / 8, 256>>>(w, ids, out);
}